// round 2
// baseline (speedup 1.0000x reference)
#include <cuda_runtime.h>
#include <math.h>
#include <stdint.h>

#define BB 8
#define LL 2048
#define DD 512
#define HH 8
#define DH 64
#define DFF 2048
#define UU 40
#define NBH (BB*HH)

// ---------------- scratch (no allocs allowed) ----------------
__device__ float g_q[NBH*LL*DH];     // [bh][l][d]
__device__ float g_k[NBH*LL*DH];
__device__ float g_v[NBH*LL*DH];
__device__ float g_M[NBH*LL];
__device__ float g_ksum[NBH*DH];
__device__ float g_vmean[NBH*DH];
__device__ int   g_topidx[NBH*UU];
__device__ float g_topout[NBH*UU*DH];

// ================= Kernel 1: QKV projection =================
// C[16384,512] = X[16384,512] @ W[512,512] + b, scattered to [bh][l][dh].
// Tile 128x64, BK=16, 256 threads, 8x4 per thread.
__global__ __launch_bounds__(256) void qkv_kernel(
    const float* __restrict__ x,
    const float* __restrict__ Wq, const float* __restrict__ bq,
    const float* __restrict__ Wk, const float* __restrict__ bk,
    const float* __restrict__ Wv, const float* __restrict__ bv)
{
    const int z = blockIdx.z;
    const float* __restrict__ W    = (z==0) ? Wq : (z==1 ? Wk : Wv);
    const float* __restrict__ bias = (z==0) ? bq : (z==1 ? bk : bv);
    float* __restrict__ outp       = (z==0) ? g_q : (z==1 ? g_k : g_v);

    __shared__ float Xs[16][132];   // [kk][m]
    __shared__ float Ws[16][68];    // [kk][n]

    const int m0 = blockIdx.x * 128;
    const int n0 = blockIdx.y * 64;
    const int tid = threadIdx.x;
    const int tn = tid & 15;        // n-group (*4)
    const int tm = tid >> 4;        // m-group (*8)

    float acc[8][4];
    #pragma unroll
    for (int i = 0; i < 8; i++)
        #pragma unroll
        for (int j = 0; j < 4; j++) acc[i][j] = 0.f;

    for (int k0 = 0; k0 < 512; k0 += 16) {
        #pragma unroll
        for (int it = 0; it < 2; it++) {
            int idx = tid + it*256;          // 512 float4
            int r = idx >> 2, c = idx & 3;
            float4 xv = *(const float4*)&x[(size_t)(m0 + r)*512 + k0 + c*4];
            Xs[c*4+0][r] = xv.x; Xs[c*4+1][r] = xv.y;
            Xs[c*4+2][r] = xv.z; Xs[c*4+3][r] = xv.w;
        }
        {
            int r = tid >> 4, c = tid & 15;  // 256 float4
            float4 wv = *(const float4*)&W[(size_t)(k0 + r)*512 + n0 + c*4];
            *(float4*)&Ws[r][c*4] = wv;
        }
        __syncthreads();
        #pragma unroll
        for (int kk = 0; kk < 16; kk++) {
            float4 a0 = *(float4*)&Xs[kk][tm*8];
            float4 a1 = *(float4*)&Xs[kk][tm*8+4];
            float4 b0 = *(float4*)&Ws[kk][tn*4];
            float am[8] = {a0.x,a0.y,a0.z,a0.w,a1.x,a1.y,a1.z,a1.w};
            float bn[4] = {b0.x,b0.y,b0.z,b0.w};
            #pragma unroll
            for (int i = 0; i < 8; i++)
                #pragma unroll
                for (int j = 0; j < 4; j++)
                    acc[i][j] = fmaf(am[i], bn[j], acc[i][j]);
        }
        __syncthreads();
    }

    const int h = n0 >> 6;                    // BN==dh: one head per n-tile
    float4 b4 = *(const float4*)&bias[n0 + tn*4];
    #pragma unroll
    for (int i = 0; i < 8; i++) {
        int r  = m0 + tm*8 + i;               // global token row
        int bb = r >> 11, l = r & 2047;
        float4 o4 = make_float4(acc[i][0]+b4.x, acc[i][1]+b4.y,
                                acc[i][2]+b4.z, acc[i][3]+b4.w);
        *(float4*)&outp[((size_t)(bb*HH + h)*LL + l)*64 + tn*4] = o4;
    }
}

// ================= Kernel 2: key-sum & value-mean =================
__global__ __launch_bounds__(256) void stats_kernel()
{
    const int bh = blockIdx.x;
    const int tid = threadIdx.x;
    const int d = tid & 63, p = tid >> 6;     // 4 partial chunks
    float ks = 0.f, vs = 0.f;
    for (int s = p*512; s < p*512 + 512; s++) {
        ks += g_k[((size_t)bh*LL + s)*64 + d];
        vs += g_v[((size_t)bh*LL + s)*64 + d];
    }
    __shared__ float rk[256], rv[256];
    rk[tid] = ks; rv[tid] = vs;
    __syncthreads();
    if (p == 0) {
        float K4 = rk[d] + rk[64+d] + rk[128+d] + rk[192+d];
        float V4 = rv[d] + rv[64+d] + rv[128+d] + rv[192+d];
        g_ksum[bh*64 + d]  = K4;
        g_vmean[bh*64 + d] = V4 * (1.0f/LL);
    }
}

// ================= Kernel 3: QK^T row-max pass, M = max - mean =================
// Per block: 128 queries x all 2048 keys (tiles of 128). Transposed smem
// ([d][row]) so compute reads are float4 & conflict-free.
__global__ __launch_bounds__(256,2) void maxpass_kernel()
{
    extern __shared__ float dsm[];
    float* Qs = dsm;                 // [64][128]
    float* Ks = dsm + 64*128;        // [64][128]
    float* ks = dsm + 2*64*128;      // [64]

    const int bh  = blockIdx.y;
    const int q0  = blockIdx.x * 128;
    const int tid = threadIdx.x;
    const int tx  = tid & 15;        // k-group (*8)
    const int ty  = tid >> 4;        // q-group (*8)

    if (tid < 64) ks[tid] = g_ksum[bh*64 + tid];

    // load Q transposed: thread-major over row index -> conflict-free stores
    #pragma unroll
    for (int it = 0; it < 8; it++) {
        int idx = tid + it*256;      // 2048 float4
        int qq = idx & 127, d4 = idx >> 7;
        float4 v = *(const float4*)&g_q[((size_t)bh*LL + q0 + qq)*64 + d4*4];
        Qs[(4*d4+0)*128 + qq] = v.x; Qs[(4*d4+1)*128 + qq] = v.y;
        Qs[(4*d4+2)*128 + qq] = v.z; Qs[(4*d4+3)*128 + qq] = v.w;
    }

    float rmax[8];
    #pragma unroll
    for (int i = 0; i < 8; i++) rmax[i] = -INFINITY;

    for (int kt = 0; kt < LL/128; kt++) {
        __syncthreads();
        #pragma unroll
        for (int it = 0; it < 8; it++) {
            int idx = tid + it*256;
            int ss = idx & 127, d4 = idx >> 7;
            float4 v = *(const float4*)&g_k[((size_t)bh*LL + kt*128 + ss)*64 + d4*4];
            Ks[(4*d4+0)*128 + ss] = v.x; Ks[(4*d4+1)*128 + ss] = v.y;
            Ks[(4*d4+2)*128 + ss] = v.z; Ks[(4*d4+3)*128 + ss] = v.w;
        }
        __syncthreads();

        float acc[8][8];
        #pragma unroll
        for (int i = 0; i < 8; i++)
            #pragma unroll
            for (int j = 0; j < 8; j++) acc[i][j] = 0.f;

        #pragma unroll 4
        for (int kk = 0; kk < 64; kk++) {
            float4 qa = *(float4*)&Qs[kk*128 + ty*8];
            float4 qb = *(float4*)&Qs[kk*128 + ty*8 + 4];
            float4 ka = *(float4*)&Ks[kk*128 + tx*8];
            float4 kb = *(float4*)&Ks[kk*128 + tx*8 + 4];
            float am[8] = {qa.x,qa.y,qa.z,qa.w,qb.x,qb.y,qb.z,qb.w};
            float bm[8] = {ka.x,ka.y,ka.z,ka.w,kb.x,kb.y,kb.z,kb.w};
            #pragma unroll
            for (int i = 0; i < 8; i++)
                #pragma unroll
                for (int j = 0; j < 8; j++)
                    acc[i][j] = fmaf(am[i], bm[j], acc[i][j]);
        }
        #pragma unroll
        for (int i = 0; i < 8; i++) {
            float m = acc[i][0];
            #pragma unroll
            for (int j = 1; j < 8; j++) m = fmaxf(m, acc[i][j]);
            rmax[i] = fmaxf(rmax[i], m);
        }
    }

    // q . ksum (partial over this thread's 4 d's), fused with max reduce
    float dotv[8];
    #pragma unroll
    for (int i = 0; i < 8; i++) dotv[i] = 0.f;
    #pragma unroll
    for (int c = 0; c < 4; c++) {
        float kv = ks[tx*4 + c];
        #pragma unroll
        for (int i = 0; i < 8; i++)
            dotv[i] = fmaf(Qs[(tx*4+c)*128 + ty*8 + i], kv, dotv[i]);
    }
    #pragma unroll
    for (int i = 0; i < 8; i++) {
        float m = rmax[i], dsum = dotv[i];
        #pragma unroll
        for (int off = 8; off > 0; off >>= 1) {
            m    = fmaxf(m, __shfl_xor_sync(0xffffffffu, m, off, 16));
            dsum +=          __shfl_xor_sync(0xffffffffu, dsum, off, 16);
        }
        if (tx == 0)
            g_M[(size_t)bh*LL + q0 + ty*8 + i] =
                (m - dsum*(1.0f/LL)) * 0.125f;   // (max - mean) / sqrt(dh)
    }
}

// ================= Kernel 4: top-40 selection per (b,h) =================
__global__ __launch_bounds__(256) void topk_kernel()
{
    const int bh = blockIdx.x, tid = threadIdx.x;
    __shared__ float vals[LL];
    __shared__ float rv[256];
    __shared__ int   ri[256];
    for (int i = tid; i < LL; i += 256) vals[i] = g_M[(size_t)bh*LL + i];
    __syncthreads();
    for (int r = 0; r < UU; r++) {
        float bv = -INFINITY; int bi = 0;
        for (int i = tid; i < LL; i += 256) {
            float v = vals[i];
            if (v > bv) { bv = v; bi = i; }
        }
        rv[tid] = bv; ri[tid] = bi;
        __syncthreads();
        for (int s = 128; s > 0; s >>= 1) {
            if (tid < s) {
                if (rv[tid+s] > rv[tid] ||
                    (rv[tid+s] == rv[tid] && ri[tid+s] < ri[tid])) {
                    rv[tid] = rv[tid+s]; ri[tid] = ri[tid+s];
                }
            }
            __syncthreads();
        }
        if (tid == 0) { g_topidx[bh*UU + r] = ri[0]; vals[ri[0]] = -INFINITY; }
        __syncthreads();
    }
}

// ================= Kernel 5: full attention for active queries =================
__global__ __launch_bounds__(256) void topattn_kernel()
{
    const int bh = blockIdx.y, r = blockIdx.x, tid = threadIdx.x;
    __shared__ float sc[LL];
    __shared__ float qrow[64];
    __shared__ float red[256];
    __shared__ float s_mx, s_sum;

    const int l = g_topidx[bh*UU + r];
    if (tid < 16) {
        float4 qv = *(const float4*)&g_q[((size_t)bh*LL + l)*64 + tid*4];
        *(float4*)&qrow[tid*4] = qv;
    }
    __syncthreads();

    float lmax = -INFINITY;
    #pragma unroll
    for (int it = 0; it < 8; it++) {
        int s = tid + it*256;
        const float4* kp = (const float4*)&g_k[((size_t)bh*LL + s)*64];
        float dot = 0.f;
        #pragma unroll
        for (int c = 0; c < 16; c++) {
            float4 kv = kp[c];
            dot = fmaf(kv.x, qrow[4*c+0], dot);
            dot = fmaf(kv.y, qrow[4*c+1], dot);
            dot = fmaf(kv.z, qrow[4*c+2], dot);
            dot = fmaf(kv.w, qrow[4*c+3], dot);
        }
        dot *= 0.125f;
        sc[s] = dot;
        lmax = fmaxf(lmax, dot);
    }
    red[tid] = lmax; __syncthreads();
    for (int s = 128; s > 0; s >>= 1) {
        if (tid < s) red[tid] = fmaxf(red[tid], red[tid+s]);
        __syncthreads();
    }
    if (tid == 0) s_mx = red[0];
    __syncthreads();

    float lsum = 0.f;
    #pragma unroll
    for (int it = 0; it < 8; it++) {
        int s = tid + it*256;
        float p = expf(sc[s] - s_mx);
        sc[s] = p; lsum += p;
    }
    red[tid] = lsum; __syncthreads();
    for (int s = 128; s > 0; s >>= 1) {
        if (tid < s) red[tid] += red[tid+s];
        __syncthreads();
    }
    if (tid == 0) s_sum = red[0];
    __syncthreads();

    const int d = tid & 63, c = tid >> 6;
    float acc = 0.f;
    for (int s = c*512; s < c*512 + 512; s++)
        acc = fmaf(sc[s], g_v[((size_t)bh*LL + s)*64 + d], acc);
    red[tid] = acc; __syncthreads();
    if (c == 0) {
        float o = (red[d] + red[64+d] + red[128+d] + red[192+d]) / s_sum;
        g_topout[((size_t)bh*UU + r)*64 + d] = o;
    }
}

// ================= Kernel 6: decoder tail (per-batch) =================
__global__ __launch_bounds__(256) void final_kernel(
    const float* __restrict__ Wo, const float* __restrict__ bo,
    const float* __restrict__ W1, const float* __restrict__ b1,
    const float* __restrict__ W2, const float* __restrict__ b2,
    const float* __restrict__ ga1, const float* __restrict__ be1,
    const float* __restrict__ ga2, const float* __restrict__ be2,
    const float* __restrict__ Wout, const float* __restrict__ bout,
    float* __restrict__ d_out)
{
    const int b = blockIdx.x, tid = threadIdx.x;
    __shared__ float ctxm[512], av[512], yv[512], ffv[2048], ov[512], red[256];
    __shared__ float s_m, s_inv;

    // ctx mean = ((L-u)*mean(v) + sum_u top_out)/L
    #pragma unroll
    for (int k = 0; k < 2; k++) {
        int d = tid + k*256;
        int h = d >> 6, dd = d & 63;
        int bh = b*HH + h;
        float val = g_vmean[bh*64 + dd] * (float)(LL - UU);
        for (int r = 0; r < UU; r++)
            val += g_topout[((size_t)bh*UU + r)*64 + dd];
        ctxm[d] = val * (1.0f/LL);
    }
    __syncthreads();

    // a = ctxm @ Wo + bo
    #pragma unroll
    for (int k = 0; k < 2; k++) {
        int d = tid + k*256;
        float acc = 0.f;
        for (int e = 0; e < 512; e++)
            acc = fmaf(ctxm[e], Wo[(size_t)e*512 + d], acc);
        av[d] = acc + bo[d];
    }
    __syncthreads();

    // LN1 on 2a
    red[tid] = 2.f*av[tid] + 2.f*av[tid+256];
    __syncthreads();
    for (int s = 128; s > 0; s >>= 1) { if (tid < s) red[tid] += red[tid+s]; __syncthreads(); }
    if (tid == 0) s_m = red[0] * (1.0f/512.f);
    __syncthreads();
    {
        float t0 = 2.f*av[tid] - s_m, t1 = 2.f*av[tid+256] - s_m;
        red[tid] = t0*t0 + t1*t1;
        __syncthreads();
        for (int s = 128; s > 0; s >>= 1) { if (tid < s) red[tid] += red[tid+s]; __syncthreads(); }
        if (tid == 0) s_inv = 1.0f / sqrtf(red[0]*(1.0f/512.f) + 1e-5f);
        __syncthreads();
        yv[tid]     = t0 * s_inv * ga1[tid]     + be1[tid];
        yv[tid+256] = t1 * s_inv * ga1[tid+256] + be1[tid+256];
    }
    __syncthreads();

    // ff = relu(y @ W1^T + b1)
    #pragma unroll
    for (int it = 0; it < 8; it++) {
        int f = tid + it*256;
        const float4* wp = (const float4*)&W1[(size_t)f*512];
        float acc = 0.f;
        #pragma unroll 8
        for (int c = 0; c < 128; c++) {
            float4 w = wp[c];
            acc = fmaf(w.x, yv[4*c+0], acc);
            acc = fmaf(w.y, yv[4*c+1], acc);
            acc = fmaf(w.z, yv[4*c+2], acc);
            acc = fmaf(w.w, yv[4*c+3], acc);
        }
        ffv[f] = fmaxf(acc + b1[f], 0.f);
    }
    __syncthreads();

    // z = ff @ W2^T + b2 ; pre-LN x2 = y + z
    #pragma unroll
    for (int k = 0; k < 2; k++) {
        int d = tid + k*256;
        const float4* wp = (const float4*)&W2[(size_t)d*2048];
        float acc = 0.f;
        #pragma unroll 8
        for (int c = 0; c < 512; c++) {
            float4 w = wp[c];
            acc = fmaf(w.x, ffv[4*c+0], acc);
            acc = fmaf(w.y, ffv[4*c+1], acc);
            acc = fmaf(w.z, ffv[4*c+2], acc);
            acc = fmaf(w.w, ffv[4*c+3], acc);
        }
        ov[d] = yv[d] + acc + b2[d];           // pre-LN
    }
    __syncthreads();

    // LN2
    red[tid] = ov[tid] + ov[tid+256];
    __syncthreads();
    for (int s = 128; s > 0; s >>= 1) { if (tid < s) red[tid] += red[tid+s]; __syncthreads(); }
    if (tid == 0) s_m = red[0] * (1.0f/512.f);
    __syncthreads();
    {
        float t0 = ov[tid] - s_m, t1 = ov[tid+256] - s_m;
        red[tid] = t0*t0 + t1*t1;
        __syncthreads();
        for (int s = 128; s > 0; s >>= 1) { if (tid < s) red[tid] += red[tid+s]; __syncthreads(); }
        if (tid == 0) s_inv = 1.0f / sqrtf(red[0]*(1.0f/512.f) + 1e-5f);
        __syncthreads();
        float o0 = t0 * s_inv * ga2[tid]     + be2[tid];
        float o1 = t1 * s_inv * ga2[tid+256] + be2[tid+256];
        ov[tid] = o0; ov[tid+256] = o1;
        d_out[BB + (size_t)b*512 + tid]       = o0;
        d_out[BB + (size_t)b*512 + tid + 256] = o1;
    }
    __syncthreads();

    // forecast = out @ Wout + bout
    red[tid] = ov[tid]*Wout[tid] + ov[tid+256]*Wout[tid+256];
    __syncthreads();
    for (int s = 128; s > 0; s >>= 1) { if (tid < s) red[tid] += red[tid+s]; __syncthreads(); }
    if (tid == 0) d_out[b] = red[0] + bout[0];
}

// ================= host launcher =================
extern "C" void kernel_launch(void* const* d_in, const int* in_sizes, int n_in,
                              void* d_out, int out_size)
{
    const float* x    = (const float*)d_in[0];
    const float* Wq   = (const float*)d_in[1];
    const float* bq   = (const float*)d_in[2];
    const float* Wk   = (const float*)d_in[3];
    const float* bk   = (const float*)d_in[4];
    const float* Wv   = (const float*)d_in[5];
    const float* bv   = (const float*)d_in[6];
    const float* Wo   = (const float*)d_in[7];
    const float* bo   = (const float*)d_in[8];
    const float* W1   = (const float*)d_in[9];
    const float* b1   = (const float*)d_in[10];
    const float* W2   = (const float*)d_in[11];
    const float* b2   = (const float*)d_in[12];
    const float* ga1  = (const float*)d_in[13];
    const float* be1  = (const float*)d_in[14];
    const float* ga2  = (const float*)d_in[15];
    const float* be2  = (const float*)d_in[16];
    const float* Wout = (const float*)d_in[17];
    const float* bout = (const float*)d_in[18];
    float* out = (float*)d_out;

    static bool attr_done = false;
    const int dyn_smem = (2*64*128 + 64) * (int)sizeof(float);   // 65,792 B
    if (!attr_done) {
        cudaFuncSetAttribute(maxpass_kernel,
                             cudaFuncAttributeMaxDynamicSharedMemorySize, dyn_smem);
        attr_done = true;
    }

    dim3 gq(128, 8, 3);
    qkv_kernel<<<gq, 256>>>(x, Wq, bq, Wk, bk, Wv, bv);
    stats_kernel<<<NBH, 256>>>();
    maxpass_kernel<<<dim3(LL/128, NBH), 256, dyn_smem>>>();
    topk_kernel<<<NBH, 256>>>();
    topattn_kernel<<<dim3(UU, NBH), 256>>>();
    final_kernel<<<BB, 256>>>(Wo, bo, W1, b1, W2, b2,
                              ga1, be1, ga2, be2, Wout, bout, out);
}